// round 10
// baseline (speedup 1.0000x reference)
#include <cuda_runtime.h>
#include <cstdint>

#define Bn 32
#define Hn 56
#define Wn 56
#define Cn 256
#define RS (Wn * Cn)
#define NTILES 1792            // 32 b x 4 hq x 14 wq
#define NBLK   608             // 152 SMs x 4 resident blocks

typedef unsigned long long ull;
typedef unsigned int u32;

// ---- packed f32x2 helpers (Blackwell FFMA2 path: only reachable via PTX) ----
__device__ __forceinline__ ull fma2(ull a, ull b, ull c) {
    ull d; asm("fma.rn.f32x2 %0, %1, %2, %3;" : "=l"(d) : "l"(a), "l"(b), "l"(c)); return d;
}
__device__ __forceinline__ ull mul2(ull a, ull b) {
    ull d; asm("mul.rn.f32x2 %0, %1, %2;" : "=l"(d) : "l"(a), "l"(b)); return d;
}
__device__ __forceinline__ ull add2(ull a, ull b) {
    ull d; asm("add.rn.f32x2 %0, %1, %2;" : "=l"(d) : "l"(a), "l"(b)); return d;
}
__device__ __forceinline__ ull pk2(u32 lo, u32 hi) {
    ull d; asm("mov.b64 %0, {%1, %2};" : "=l"(d) : "r"(lo), "r"(hi)); return d;
}
__device__ __forceinline__ ull dup2(u32 v) {
    ull d; asm("mov.b64 %0, {%1, %1};" : "=l"(d) : "r"(v)); return d;
}
__device__ __forceinline__ void up2(ull v, u32 &lo, u32 &hi) {
    asm("mov.b64 {%0, %1}, %2;" : "=r"(lo), "=r"(hi) : "l"(v));
}

__global__ void __launch_bounds__(128, 4) gdn_kernel(
    const float* __restrict__ x,  const float* __restrict__ gk,
    const float* __restrict__ gs, const float* __restrict__ beta,
    const float* __restrict__ bo, const float* __restrict__ go,
    float* __restrict__ out)
{
    const int ct  = threadIdx.x;     // channel-thread: channels [2ct, 2ct+2)
    const int cb  = ct * 2;
    const int qid = ct & 3;          // position within 4-thread group quad

    // ======== tile-invariant state: loaded ONCE per persistent block ========
    ull Wp[8];                       // Pk weights, pre-permuted to shuffle order
#pragma unroll
    for (int j = 0; j < 4; j++) {
        const int src = qid ^ j;
        Wp[2 * j]     = *(const ull*)(gk + (2 * src)     * Cn + cb);
        Wp[2 * j + 1] = *(const ull*)(gk + (2 * src + 1) * Cn + cb);
    }
    const int tapi[8] = {0, 1, 2, 3, 5, 6, 7, 8};   // 3x3 minus center
    ull kp[8];
#pragma unroll
    for (int t = 0; t < 8; t++)
        kp[t] = *(const ull*)(gs + tapi[t] * Cn + cb);

    float2 bt = *(const float2*)(beta + cb);
    const ull bp  = pk2(__float_as_uint(bt.x + 1e-6f), __float_as_uint(bt.y + 1e-6f));
    const ull gov = *(const ull*)(go + cb);
    const ull bov = *(const ull*)(bo + cb);

    // ======== persistent loop over w-quad tiles ========
    for (int tile = blockIdx.x; tile < NTILES; tile += NBLK) {
        int bi = tile;
        const int wq = bi % 14; bi /= 14;   // w-quad: output cols w0..w0+3
        const int hq = bi & 3;  bi >>= 2;
        const int b  = bi;
        const int w0 = wq * 4;
        const int h0 = hq * 14;
        const bool wl = (wq > 0), wr = (wq < 13);

        const float* xw = x   + (((size_t)b * Hn) * Wn + w0) * Cn + cb;
        float*       ob = out + (((size_t)b * Hn) * Wn + w0) * Cn + cb;

        // raw load of one row's 6 columns (w0-1 .. w0+4)
        auto ldrow = [&](int hg, ull (&f)[6]) {
#pragma unroll
            for (int q = 0; q < 6; q++) f[q] = 0;
            if (hg >= 0 && hg < Hn) {
                const float* p = xw + (size_t)hg * RS;
                if (wl) f[0] = *(const ull*)(p - Cn);
                f[1] = *(const ull*)(p);
                f[2] = *(const ull*)(p + Cn);
                f[3] = *(const ull*)(p + 2 * Cn);
                f[4] = *(const ull*)(p + 3 * Cn);
                if (wr) f[5] = *(const ull*)(p + 4 * Cn);
            }
        };

        // squared window rows a(h-1), b(h), c(h+1) x 6 cols; raw centers; prefetch
        ull aS[6], bS[6], cS[6];
        ull rb[4], rc[4];            // raw center cols, rows h and h+1
        ull pf[6];                   // raw prefetch row h+2

        {
            ull f[6];
            ldrow(h0 - 1, f);
#pragma unroll
            for (int q = 0; q < 6; q++) aS[q] = mul2(f[q], f[q]);
            ldrow(h0, f);
#pragma unroll
            for (int q = 0; q < 6; q++) bS[q] = mul2(f[q], f[q]);
#pragma unroll
            for (int q = 0; q < 4; q++) rb[q] = f[q + 1];
            ldrow(h0 + 1, f);
#pragma unroll
            for (int q = 0; q < 6; q++) cS[q] = mul2(f[q], f[q]);
#pragma unroll
            for (int q = 0; q < 4; q++) rc[q] = f[q + 1];
            ldrow(h0 + 2, pf);
        }

#pragma unroll
        for (int s = 0; s < 14; s++) {
            const int h = h0 + s;
            float* po = ob + (size_t)h * RS;

            // ---- 4 independent output columns ----
#pragma unroll
            for (int j = 0; j < 4; j++) {
                const ull sq = bS[j + 1];
                const ull vb = __shfl_xor_sync(0xffffffffu, sq, 1);
                const ull vc = __shfl_xor_sync(0xffffffffu, sq, 2);
                const ull vd = __shfl_xor_sync(0xffffffffu, sq, 3);

                u32 t0, t1;
                // Pk (2 chains)
                ull A = bp, B;
                up2(sq, t0, t1);
                A = fma2(dup2(t0), Wp[0], A);  B = mul2(dup2(t1), Wp[1]);
                up2(vb, t0, t1);
                A = fma2(dup2(t0), Wp[2], A);  B = fma2(dup2(t1), Wp[3], B);
                up2(vc, t0, t1);
                A = fma2(dup2(t0), Wp[4], A);  B = fma2(dup2(t1), Wp[5], B);
                up2(vd, t0, t1);
                A = fma2(dup2(t0), Wp[6], A);  B = fma2(dup2(t1), Wp[7], B);
                // Ps (2 chains)
                ull C = mul2(aS[j],     kp[0]);
                ull D = mul2(aS[j + 1], kp[1]);
                C = fma2(aS[j + 2], kp[2], C);
                D = fma2(bS[j],     kp[3], D);
                C = fma2(bS[j + 2], kp[4], C);
                D = fma2(cS[j],     kp[5], D);
                C = fma2(cS[j + 1], kp[6], C);
                D = fma2(cS[j + 2], kp[7], D);
                const ull acc = add2(add2(A, B), add2(C, D));

                // epilogue: x * rsqrt(acc) * gamma_o + beta_o
                up2(acc, t0, t1);
                const float r0 = rsqrtf(__uint_as_float(t0));
                const float r1 = rsqrtf(__uint_as_float(t1));
                const ull rp = pk2(__float_as_uint(r0), __float_as_uint(r1));
                *(ull*)(po + j * Cn) = fma2(mul2(rb[j], rp), gov, bov);
            }

            // ---- shift window; absorb prefetch; issue next load ----
            if (s < 13) {
#pragma unroll
                for (int q = 0; q < 6; q++) {
                    aS[q] = bS[q]; bS[q] = cS[q];
                    cS[q] = mul2(pf[q], pf[q]);
                }
#pragma unroll
                for (int q = 0; q < 4; q++) { rb[q] = rc[q]; rc[q] = pf[q + 1]; }
                // last consumed row is h0+14, loaded at s=11 -> no loads after
                if (s < 12) ldrow(h + 3, pf);
            }
        }
    }
}

extern "C" void kernel_launch(void* const* d_in, const int* in_sizes, int n_in,
                              void* d_out, int out_size) {
    const float* x    = (const float*)d_in[0];
    const float* gk   = (const float*)d_in[1];
    const float* gs   = (const float*)d_in[2];
    const float* beta = (const float*)d_in[3];
    const float* bo   = (const float*)d_in[4];
    const float* go   = (const float*)d_in[5];
    gdn_kernel<<<NBLK, 128>>>(x, gk, gs, beta, bo, go, (float*)d_out);
}